// round 16
// baseline (speedup 1.0000x reference)
#include <cuda_runtime.h>
#include <cuda_bf16.h>
#include <cstdint>
#include <math.h>

#define NN 16
#define CC 256
#define HH 64
#define WW 64
#define LL 4096
#define KK 32
#define EPSV 1e-12f
#define SPL 16   // L-splits for k_up0
#define JS  32   // j-splits for FC

// ---------------- scratch (device globals; no allocation) ----------------
__device__ __nv_bfloat16 g_xci_hi[(size_t)NN * LL * CC];  // 32 MB: NORMALIZED feature bf16 hi, [n][l][c]
__device__ __nv_bfloat16 g_xci_lo[(size_t)NN * LL * CC];  // 32 MB: NORMALIZED feature bf16 lo
__device__ float g_inv[NN * LL];              // per-pixel 1/||f||
__device__ float g_nrm[NN * LL];              // per-pixel max(||f||, eps)
__device__ float g_sa[NN * KK * LL];          // 8 MB : sa' = softmax * inv[pixel]
__device__ float g_ssumc[NN * 16 * KK];       // ssum partials per conv CTA tile
__device__ float g_up0p[SPL * NN * KK * CC];  // 8 MB : einsum partials per L-split
__device__ float g_upn[NN * KK * CC];         // fully normalized up
__device__ float g_fcp[JS * NN * CC];         // FC partials
__device__ float g_bias1[NN * CC];            // effective t1 bias
__device__ __nv_bfloat16 g_cwhi[9 * 16 * 32 * 16];  // conv W split: [tap][chunk][m][k]
__device__ __nv_bfloat16 g_cwlo[9 * 16 * 32 * 16];
__device__ __nv_bfloat16 g_w1hi[CC * CC];     // t1_w (first 256 in-chans) split
__device__ __nv_bfloat16 g_w1lo[CC * CC];
__device__ __nv_bfloat16 g_w2hi[CC * CC];     // t2_w split
__device__ __nv_bfloat16 g_w2lo[CC * CC];

static __device__ __forceinline__ uint32_t pk2(__nv_bfloat16 a, __nv_bfloat16 b) {
    return (uint32_t)__bfloat16_as_ushort(a) | ((uint32_t)__bfloat16_as_ushort(b) << 16);
}
static __device__ __forceinline__ void mma16816(float* d,
                                                uint32_t a0, uint32_t a1, uint32_t a2, uint32_t a3,
                                                uint32_t b0, uint32_t b1) {
    asm volatile("mma.sync.aligned.m16n8k16.row.col.f32.bf16.bf16.f32 "
                 "{%0,%1,%2,%3}, {%4,%5,%6,%7}, {%8,%9}, {%0,%1,%2,%3};"
                 : "+f"(d[0]), "+f"(d[1]), "+f"(d[2]), "+f"(d[3])
                 : "r"(a0), "r"(a1), "r"(a2), "r"(a3), "r"(b0), "r"(b1));
}
__device__ __forceinline__ uint32_t smem_u32(const void* p) {
    uint32_t a;
    asm("{ .reg .u64 t; cvta.to.shared.u64 t, %1; cvt.u32.u64 %0, t; }" : "=r"(a) : "l"(p));
    return a;
}
#define CP16(dst, src) asm volatile("cp.async.cg.shared.global [%0], [%1], 16;" :: "r"(dst), "l"(src) : "memory")
#define CP_COMMIT()    asm volatile("cp.async.commit_group;" ::: "memory")
#define CP_WAIT1()     asm volatile("cp.async.wait_group 1;" ::: "memory")
#define CP_WAIT0()     asm volatile("cp.async.wait_group 0;" ::: "memory")

// ---------------- kernel 1: prep — normalize in smem, write NORMALIZED split ----------------
__global__ __launch_bounds__(256) void k_prep(const float* __restrict__ f) {
    extern __shared__ float sx[];   // [256 c][68 px-pitch]
    __shared__ float part[4][64];
    __shared__ float invv[64];
    int n = blockIdx.y;
    int l0 = blockIdx.x * 64;
    int tid = threadIdx.x;
    for (int i = tid; i < 4096; i += 256) {
        int c = i >> 4, p4 = (i & 15) << 2;
        float4 v = *(const float4*)(f + ((size_t)n * CC + c) * LL + l0 + p4);
        *(float4*)&sx[c * 68 + p4] = v;
    }
    __syncthreads();
    int px = tid & 63, q = tid >> 6;
    {
        float s = 0.f;
#pragma unroll 8
        for (int j = 0; j < 64; j++) {
            float v = sx[(q * 64 + j) * 68 + px];
            s += v * v;
        }
        part[q][px] = s;
    }
    __syncthreads();
    if (tid < 64) {
        float s = part[0][tid] + part[1][tid] + part[2][tid] + part[3][tid];
        float nr = fmaxf(sqrtf(s), EPSV);
        float iv = 1.f / nr;
        invv[tid] = iv;
        g_inv[n * LL + l0 + tid] = iv;
        g_nrm[n * LL + l0 + tid] = nr;
    }
    __syncthreads();
    float iv = invv[px];
    size_t cib = ((size_t)n * LL + l0 + px) * CC + q * 64;
#pragma unroll 2
    for (int j8 = 0; j8 < 64; j8 += 8) {
        uint32_t oh[4], ol[4];
#pragma unroll
        for (int t = 0; t < 4; t++) {
            float x0 = sx[(q * 64 + j8 + 2 * t) * 68 + px] * iv;
            float x1 = sx[(q * 64 + j8 + 2 * t + 1) * 68 + px] * iv;
            __nv_bfloat16 h0 = __float2bfloat16_rn(x0), h1 = __float2bfloat16_rn(x1);
            oh[t] = pk2(h0, h1);
            ol[t] = pk2(__float2bfloat16_rn(x0 - __bfloat162float(h0)),
                        __float2bfloat16_rn(x1 - __bfloat162float(h1)));
        }
        *(uint4*)(g_xci_hi + cib + j8) = make_uint4(oh[0], oh[1], oh[2], oh[3]);
        *(uint4*)(g_xci_lo + cib + j8) = make_uint4(ol[0], ol[1], ol[2], ol[3]);
    }
}

// ---------------- prep: conv weights + t1/t2 weights, one launch ----------------
__global__ __launch_bounds__(256) void k_wprep_all(const float* __restrict__ w,
                                                   const float* __restrict__ t1w,
                                                   const float* __restrict__ t2w) {
    int b = blockIdx.x;
    int tid = threadIdx.x;
    if (b < 288) {
        int i = b * 256 + tid;
        int t = i >> 13;
        int r = i & 8191;
        int chn = r >> 9;
        int m = (r >> 4) & 31;
        int kk = r & 15;
        int c = chn * 16 + kk;
        float x = w[((size_t)m * CC + c) * 9 + t];
        __nv_bfloat16 h = __float2bfloat16_rn(x);
        g_cwhi[i] = h;
        g_cwlo[i] = __float2bfloat16_rn(x - __bfloat162float(h));
    } else {
        int i = (b - 288) * 256 + tid;
        int o = i >> 8, c = i & 255;
        {
            float x = t1w[(size_t)o * 512 + c];
            __nv_bfloat16 h = __float2bfloat16_rn(x);
            g_w1hi[i] = h;
            g_w1lo[i] = __float2bfloat16_rn(x - __bfloat162float(h));
        }
        {
            float x = t2w[i];
            __nv_bfloat16 h = __float2bfloat16_rn(x);
            g_w2hi[i] = h;
            g_w2lo[i] = __float2bfloat16_rn(x - __bfloat162float(h));
        }
    }
}

// ---------------- kernel 2: 3x3 conv (16x16 tiles) + fused softmax ----------------
__global__ __launch_bounds__(256) void k_conv_mma(const float* __restrict__ bias) {
    __shared__ __align__(16) __nv_bfloat16 hHi[18 * 18 * 16];
    __shared__ __align__(16) __nv_bfloat16 hLo[18 * 18 * 16];
    __shared__ __align__(16) __nv_bfloat16 wHi[9 * 32 * 16];
    __shared__ __align__(16) __nv_bfloat16 wLo[9 * 32 * 16];
    __shared__ float sInv[256];
    __shared__ float sred[8][33];
    __shared__ float bsm[32];
    int n = blockIdx.z;
    int ty0 = blockIdx.y * 16, tx0 = blockIdx.x * 16;
    int tid = threadIdx.x, wid = tid >> 5, lane = tid & 31;
    int g = lane >> 2, c4 = lane & 3;
    if (tid < 32) bsm[tid] = bias[tid];
    sInv[tid] = g_inv[n * LL + (ty0 + (tid >> 4)) * 64 + tx0 + (tid & 15)];

    float d[2][4][4];
#pragma unroll
    for (int mt = 0; mt < 2; mt++)
#pragma unroll
        for (int nt = 0; nt < 4; nt++)
#pragma unroll
            for (int e = 0; e < 4; e++) d[mt][nt][e] = 0.f;

#pragma unroll 1
    for (int chk = 0; chk < 16; chk++) {
        int c0 = chk * 16;
        __syncthreads();
        for (int i = tid; i < 648; i += 256) {
            int slot = i >> 1, half = i & 1;
            int y = slot / 18, x = slot - y * 18;
            int gy = ty0 + y - 1, gx = tx0 + x - 1;
            uint4 vh = make_uint4(0, 0, 0, 0), vl = make_uint4(0, 0, 0, 0);
            if ((unsigned)gy < 64u && (unsigned)gx < 64u) {
                size_t off = ((size_t)n * LL + gy * 64 + gx) * CC + c0 + half * 8;
                vh = *(const uint4*)(g_xci_hi + off);
                vl = *(const uint4*)(g_xci_lo + off);
            }
            *(uint4*)(hHi + slot * 16 + half * 8) = vh;
            *(uint4*)(hLo + slot * 16 + half * 8) = vl;
        }
        for (int i = tid; i < 576; i += 256) {
            int t = i >> 6, r = i & 63;
            ((uint4*)wHi)[t * 64 + r] = ((const uint4*)g_cwhi)[(t * 16 + chk) * 64 + r];
            ((uint4*)wLo)[t * 64 + r] = ((const uint4*)g_cwlo)[(t * 16 + chk) * 64 + r];
        }
        __syncthreads();
#pragma unroll
        for (int tap = 0; tap < 9; tap++) {
            int r = tap / 3, s = tap - 3 * (tap / 3);
            uint32_t bh[4][2], bl[4][2];
#pragma unroll
            for (int nt = 0; nt < 4; nt++) {
                int pxl = wid * 32 + nt * 8 + g;
                int y = (pxl >> 4) + r, x = (pxl & 15) + s;
                const __nv_bfloat16* ph = hHi + (y * 18 + x) * 16 + 2 * c4;
                const __nv_bfloat16* pl = hLo + (y * 18 + x) * 16 + 2 * c4;
                bh[nt][0] = *(const uint32_t*)ph;
                bh[nt][1] = *(const uint32_t*)(ph + 8);
                bl[nt][0] = *(const uint32_t*)pl;
                bl[nt][1] = *(const uint32_t*)(pl + 8);
            }
#pragma unroll
            for (int mt = 0; mt < 2; mt++) {
                const __nv_bfloat16* qh = wHi + (tap * 32 + mt * 16 + g) * 16 + 2 * c4;
                const __nv_bfloat16* ql = wLo + (tap * 32 + mt * 16 + g) * 16 + 2 * c4;
                uint32_t ah0 = *(const uint32_t*)qh;
                uint32_t ah1 = *(const uint32_t*)(qh + 128);
                uint32_t ah2 = *(const uint32_t*)(qh + 8);
                uint32_t ah3 = *(const uint32_t*)(qh + 136);
                uint32_t al0 = *(const uint32_t*)ql;
                uint32_t al1 = *(const uint32_t*)(ql + 128);
                uint32_t al2 = *(const uint32_t*)(ql + 8);
                uint32_t al3 = *(const uint32_t*)(ql + 136);
#pragma unroll
                for (int nt = 0; nt < 4; nt++) {
                    mma16816(d[mt][nt], ah0, ah1, ah2, ah3, bh[nt][0], bh[nt][1]);
                    mma16816(d[mt][nt], ah0, ah1, ah2, ah3, bl[nt][0], bl[nt][1]);
                    mma16816(d[mt][nt], al0, al1, al2, al3, bh[nt][0], bh[nt][1]);
                }
            }
        }
    }
#pragma unroll
    for (int mt = 0; mt < 2; mt++)
#pragma unroll
        for (int nt = 0; nt < 4; nt++)
#pragma unroll
            for (int e = 0; e < 4; e++)
                d[mt][nt][e] += bsm[mt * 16 + g + (e >> 1) * 8];
    float ssacc[4] = {0.f, 0.f, 0.f, 0.f};
#pragma unroll
    for (int nt = 0; nt < 4; nt++) {
#pragma unroll
        for (int e1 = 0; e1 < 2; e1++) {
            float v00 = d[0][nt][e1], v01 = d[0][nt][e1 + 2];
            float v10 = d[1][nt][e1], v11 = d[1][nt][e1 + 2];
            float m = fmaxf(fmaxf(v00, v01), fmaxf(v10, v11));
            m = fmaxf(m, __shfl_xor_sync(0xffffffffu, m, 4));
            m = fmaxf(m, __shfl_xor_sync(0xffffffffu, m, 8));
            m = fmaxf(m, __shfl_xor_sync(0xffffffffu, m, 16));
            float e00 = __expf(v00 - m), e01 = __expf(v01 - m);
            float e10 = __expf(v10 - m), e11 = __expf(v11 - m);
            float s = e00 + e01 + e10 + e11;
            s += __shfl_xor_sync(0xffffffffu, s, 4);
            s += __shfl_xor_sync(0xffffffffu, s, 8);
            s += __shfl_xor_sync(0xffffffffu, s, 16);
            float inv = 1.f / s;
            float sa00 = e00 * inv, sa01 = e01 * inv;
            float sa10 = e10 * inv, sa11 = e11 * inv;
            ssacc[0] += sa00; ssacc[1] += sa01;
            ssacc[2] += sa10; ssacc[3] += sa11;
            int px = wid * 32 + nt * 8 + 2 * c4 + e1;
            float pxinv = sInv[px];
            int gy = ty0 + (px >> 4), gx = tx0 + (px & 15);
            size_t base = ((size_t)n * KK) * LL + gy * 64 + gx;
            g_sa[base + (size_t)g * LL]        = sa00 * pxinv;
            g_sa[base + (size_t)(g + 8) * LL]  = sa01 * pxinv;
            g_sa[base + (size_t)(g + 16) * LL] = sa10 * pxinv;
            g_sa[base + (size_t)(g + 24) * LL] = sa11 * pxinv;
        }
    }
#pragma unroll
    for (int j = 0; j < 4; j++) {
        ssacc[j] += __shfl_xor_sync(0xffffffffu, ssacc[j], 1);
        ssacc[j] += __shfl_xor_sync(0xffffffffu, ssacc[j], 2);
    }
    if (c4 == 0) {
        sred[wid][g]      = ssacc[0];
        sred[wid][g + 8]  = ssacc[1];
        sred[wid][g + 16] = ssacc[2];
        sred[wid][g + 24] = ssacc[3];
    }
    __syncthreads();
    if (tid < 32) {
        float t = 0.f;
#pragma unroll
        for (int w = 0; w < 8; w++) t += sred[w][tid];
        int tile = blockIdx.y * 4 + blockIdx.x;
        g_ssumc[(n * 16 + tile) * KK + tid] = t;
    }
}

// ---------------- kernel 4: einsum partials via mma.sync — full 256-c CTA, one wave ----------------
// grid (16 n, 16 sp) = 256 CTAs, 2/SM by smem (83 KB dynamic). warp = 32k x 32c.
#define UPITCH 72
__global__ __launch_bounds__(256) void k_up0(const float* __restrict__ f) {
    extern __shared__ __align__(16) __nv_bfloat16 us[];
    __nv_bfloat16* saH = us;                    // 32 x 72
    __nv_bfloat16* saL = us + 2304;
    __nv_bfloat16* fHs = us + 4608;             // 256 x 72
    __nv_bfloat16* fLs = us + 23040;            // total 41472 elems = 82944 B
    int n = blockIdx.x;
    int sp = blockIdx.y;
    int lbase = sp * (LL / SPL);
    int tid = threadIdx.x, wid = tid >> 5, lane = tid & 31;
    int g = lane >> 2, c4 = lane & 3;
    int c0w = wid * 32;

    float d[2][4][4];
#pragma unroll
    for (int mt = 0; mt < 2; mt++)
#pragma unroll
        for (int nt = 0; nt < 4; nt++)
#pragma unroll
            for (int e = 0; e < 4; e++) d[mt][nt][e] = 0.f;

#pragma unroll 1
    for (int ch = 0; ch < 4; ch++) {
        int l0 = lbase + ch * 64;
        __syncthreads();
        for (int i = tid; i < 512; i += 256) {
            int k = i >> 4, l4 = (i & 15) << 2;
            float4 v = *(const float4*)(g_sa + (size_t)(n * KK + k) * LL + l0 + l4);
            __nv_bfloat16 h0 = __float2bfloat16_rn(v.x), h1 = __float2bfloat16_rn(v.y);
            __nv_bfloat16 h2 = __float2bfloat16_rn(v.z), h3 = __float2bfloat16_rn(v.w);
            *(uint2*)&saH[k * UPITCH + l4] = make_uint2(pk2(h0, h1), pk2(h2, h3));
            *(uint2*)&saL[k * UPITCH + l4] = make_uint2(
                pk2(__float2bfloat16_rn(v.x - __bfloat162float(h0)),
                    __float2bfloat16_rn(v.y - __bfloat162float(h1))),
                pk2(__float2bfloat16_rn(v.z - __bfloat162float(h2)),
                    __float2bfloat16_rn(v.w - __bfloat162float(h3))));
        }
        for (int i = tid; i < 4096; i += 256) {
            int c = i >> 4, l4 = (i & 15) << 2;
            float4 v = *(const float4*)(f + (size_t)(n * CC + c) * LL + l0 + l4);
            __nv_bfloat16 h0 = __float2bfloat16_rn(v.x), h1 = __float2bfloat16_rn(v.y);
            __nv_bfloat16 h2 = __float2bfloat16_rn(v.z), h3 = __float2bfloat16_rn(v.w);
            *(uint2*)&fHs[c * UPITCH + l4] = make_uint2(pk2(h0, h1), pk2(h2, h3));
            *(uint2*)&fLs[c * UPITCH + l4] = make_uint2(
                pk2(__float2bfloat16_rn(v.x - __bfloat162float(h0)),
                    __float2bfloat16_rn(v.y - __bfloat162float(h1))),
                pk2(__float2bfloat16_rn(v.z - __bfloat162float(h2)),
                    __float2bfloat16_rn(v.w - __bfloat162float(h3))));
        }
        __syncthreads();
#pragma unroll
        for (int ls = 0; ls < 4; ls++) {
            int cb = ls * 16 + 2 * c4;
            uint32_t aH[2][4], aL[2][4];
#pragma unroll
            for (int mt = 0; mt < 2; mt++) {
                int r0 = mt * 16 + g;
                aH[mt][0] = *(const uint32_t*)&saH[r0 * UPITCH + cb];
                aH[mt][1] = *(const uint32_t*)&saH[(r0 + 8) * UPITCH + cb];
                aH[mt][2] = *(const uint32_t*)&saH[r0 * UPITCH + cb + 8];
                aH[mt][3] = *(const uint32_t*)&saH[(r0 + 8) * UPITCH + cb + 8];
                aL[mt][0] = *(const uint32_t*)&saL[r0 * UPITCH + cb];
                aL[mt][1] = *(const uint32_t*)&saL[(r0 + 8) * UPITCH + cb];
                aL[mt][2] = *(const uint32_t*)&saL[r0 * UPITCH + cb + 8];
                aL[mt][3] = *(const uint32_t*)&saL[(r0 + 8) * UPITCH + cb + 8];
            }
#pragma unroll
            for (int nt = 0; nt < 4; nt++) {
                int crow = c0w + nt * 8 + g;
                uint32_t bH0 = *(const uint32_t*)&fHs[crow * UPITCH + cb];
                uint32_t bH1 = *(const uint32_t*)&fHs[crow * UPITCH + cb + 8];
                uint32_t bL0 = *(const uint32_t*)&fLs[crow * UPITCH + cb];
                uint32_t bL1 = *(const uint32_t*)&fLs[crow * UPITCH + cb + 8];
#pragma unroll
                for (int mt = 0; mt < 2; mt++) {
                    mma16816(d[mt][nt], aH[mt][0], aH[mt][1], aH[mt][2], aH[mt][3], bH0, bH1);
                    mma16816(d[mt][nt], aH[mt][0], aH[mt][1], aH[mt][2], aH[mt][3], bL0, bL1);
                    mma16816(d[mt][nt], aL[mt][0], aL[mt][1], aL[mt][2], aL[mt][3], bH0, bH1);
                }
            }
        }
    }
    size_t ob = ((size_t)sp * NN + n) * (KK * CC);
#pragma unroll
    for (int mt = 0; mt < 2; mt++) {
#pragma unroll
        for (int nt = 0; nt < 4; nt++) {
            int k0 = mt * 16 + g;
            int cc = c0w + nt * 8 + 2 * c4;
            *(float2*)(g_up0p + ob + (size_t)k0 * CC + cc) = make_float2(d[mt][nt][0], d[mt][nt][1]);
            *(float2*)(g_up0p + ob + (size_t)(k0 + 8) * CC + cc) = make_float2(d[mt][nt][2], d[mt][nt][3]);
        }
    }
}

// ---------------- kernel 5a: reduce partials + centroid-sub + norms -> g_upn ----------------
__global__ __launch_bounds__(256) void k_upnorm(const float* __restrict__ cent) {
    int n = blockIdx.x;
    int tid = threadIdx.x;
    int lane = tid & 31, wp = tid >> 5;
    __shared__ float upn[KK * CC];
    __shared__ float red[8];
    __shared__ float ssk[KK];
    __shared__ float gtot;

    if (tid < KK) {
        float s = 0.f;
#pragma unroll
        for (int t = 0; t < 16; t++)
            s += g_ssumc[(n * 16 + t) * KK + tid];
        ssk[tid] = s;
    }
    __syncthreads();

    for (int k = wp; k < KK; k += 8) {
        float sk = ssk[k];
        float vals[8];
        float sq = 0.f;
#pragma unroll
        for (int j = 0; j < 8; j++) {
            int c = lane + 32 * j;
            float u = 0.f;
#pragma unroll
            for (int sp = 0; sp < SPL; sp++)
                u += g_up0p[((size_t)sp * NN + n) * (KK * CC) + k * CC + c];
            u -= sk * cent[k * CC + c];
            vals[j] = u;
            sq += u * u;
        }
        for (int off = 16; off; off >>= 1) sq += __shfl_xor_sync(0xffffffffu, sq, off);
        float inv = 1.f / fmaxf(sqrtf(sq), EPSV);
#pragma unroll
        for (int j = 0; j < 8; j++) upn[k * CC + lane + 32 * j] = vals[j] * inv;
    }
    __syncthreads();
    float gs = 0.f;
#pragma unroll 4
    for (int j = 0; j < 32; j++) {
        float v = upn[j * 256 + tid];
        gs += v * v;
    }
    for (int off = 16; off; off >>= 1) gs += __shfl_xor_sync(0xffffffffu, gs, off);
    if (!lane) red[wp] = gs;
    __syncthreads();
    if (tid == 0) {
        float t = 0.f;
        for (int i = 0; i < 8; i++) t += red[i];
        gtot = 1.f / fmaxf(sqrtf(t), EPSV);
    }
    __syncthreads();
    float ginv = gtot;
#pragma unroll 4
    for (int j = 0; j < 32; j++)
        g_upn[n * (KK * CC) + j * 256 + tid] = upn[j * 256 + tid] * ginv;
}

// ---------------- kernel 5b: FC partials ----------------
#define FCP 264
__global__ __launch_bounds__(256) void k_fc(const float* __restrict__ wfc) {
    __shared__ float ws[16][FCP];
    __shared__ float us2[16][FCP];
    int ot = blockIdx.x * 16;
    int j0 = blockIdx.y * 256;
    int tid = threadIdx.x;
    for (int i = tid; i < 16 * 64; i += 256) {
        int row = i >> 6, j4 = (i & 63) << 2;
        *(float4*)&ws[row][j4] = *(const float4*)(wfc + (size_t)(ot + row) * (KK * CC) + j0 + j4);
        *(float4*)&us2[row][j4] = *(const float4*)(g_upn + (size_t)row * (KK * CC) + j0 + j4);
    }
    __syncthreads();
    int o = tid & 15, n = tid >> 4;
    float s = 0.f;
#pragma unroll 8
    for (int jj = 0; jj < 64; jj++) {
        float4 a = *(const float4*)&ws[o][jj * 4];
        float4 b = *(const float4*)&us2[n][jj * 4];
        s += a.x * b.x + a.y * b.y + a.z * b.z + a.w * b.w;
    }
    g_fcp[(size_t)(blockIdx.y * NN + n) * CC + ot + o] = s;
}

// ---------------- kernel 5c: FC reduce + effective t1 bias (merged) ----------------
__global__ __launch_bounds__(256) void k_bias1(const float* __restrict__ bfc,
                                               const float* __restrict__ t1w,
                                               const float* __restrict__ t1b) {
    __shared__ float ufc[CC];
    int n = blockIdx.x;
    int tid = threadIdx.x;
    float s = 0.f;
#pragma unroll
    for (int js = 0; js < JS; js++)
        s += g_fcp[(size_t)(js * NN + n) * CC + tid];
    ufc[tid] = s + bfc[tid];
    __syncthreads();
    float b = 0.f;
#pragma unroll 8
    for (int c = 0; c < CC; c += 4) {
        float4 wv = *(const float4*)(t1w + (size_t)tid * 512 + 256 + c);
        b += wv.x * ufc[c] + wv.y * ufc[c + 1] + wv.z * ufc[c + 2] + wv.w * ufc[c + 3];
    }
    g_bias1[n * CC + tid] = t1b[tid] + b;
}

// ---------------- kernel 6: mma.sync transform, cp.async double-buffered ----------------
#define W2P    80
#define SM_WOF 2048
#define SM_XOF 83968
#define SM_HOF 104448
#define SM_TOT 174080
#define HPITCH 528

__global__ __launch_bounds__(256, 1) void k_transform_mma(const float* __restrict__ t2b,
                                                          float* __restrict__ out) {
    extern __shared__ char sm[];
    __shared__ float nrms[64];
    uint32_t sb = smem_u32(sm);
    float* b1s = (float*)sm;
    float* b2s = (float*)(sm + 1024);
    int tid = threadIdx.x;
    int wid = tid >> 5, lane = tid & 31;
    int g = lane >> 2, c4 = lane & 3;
    int ow = (wid >> 1) * 64;
    int pxw = (wid & 1) * 32;
    int n = blockIdx.y;
    int p0 = blockIdx.x * 64;

    b1s[tid] = g_bias1[n * CC + tid];
    b2s[tid] = t2b[tid];
    if (tid < 64) nrms[tid] = g_nrm[n * LL + p0 + tid];

#define ISSUE_W(whi, wlo, kc, b)                                                   \
    do {                                                                           \
        uint32_t wb_ = sb + SM_WOF + (b) * 40960;                                  \
        for (int i_ = tid; i_ < 2048; i_ += 256) {                                 \
            int half_ = i_ >> 10;                                                  \
            int r_ = i_ & 1023;                                                    \
            int o_ = r_ >> 2, j_ = r_ & 3;                                         \
            const __nv_bfloat16* s_ = (half_ ? (wlo) : (whi)) + o_ * 256 + (kc) * 32 + j_ * 8; \
            CP16(wb_ + half_ * 20480 + o_ * W2P + j_ * 16, s_);                    \
        }                                                                          \
    } while (0)
#define ISSUE_X(kc, b)                                                             \
    do {                                                                           \
        uint32_t xb_ = sb + SM_XOF + (b) * 10240;                                  \
        for (int i_ = tid; i_ < 512; i_ += 256) {                                  \
            int half_ = i_ >> 8;                                                   \
            int r_ = i_ & 255;                                                     \
            int px_ = r_ >> 2, j_ = r_ & 3;                                        \
            const __nv_bfloat16* s_ = (half_ ? g_xci_lo : g_xci_hi)                \
                + ((size_t)n * LL + p0 + px_) * CC + (kc) * 32 + j_ * 8;           \
            CP16(xb_ + half_ * 5120 + px_ * W2P + j_ * 16, s_);                    \
        }                                                                          \
    } while (0)

    float d[4][4][4];
#pragma unroll
    for (int mt = 0; mt < 4; mt++)
#pragma unroll
        for (int nt = 0; nt < 4; nt++)
#pragma unroll
            for (int e = 0; e < 4; e++) d[mt][nt][e] = 0.f;

    // ================= stage 1: D1 = W1 @ X (X normalized; rescale at epilogue) =================
    ISSUE_W(g_w1hi, g_w1lo, 0, 0);
    ISSUE_X(0, 0);
    CP_COMMIT();
#pragma unroll 1
    for (int kc = 0; kc < 8; kc++) {
        int b = kc & 1;
        if (kc < 7) {
            ISSUE_W(g_w1hi, g_w1lo, kc + 1, 1 - b);
            ISSUE_X(kc + 1, 1 - b);
            CP_COMMIT();
            CP_WAIT1();
        } else {
            CP_WAIT0();
        }
        __syncthreads();
        const char* wb = sm + SM_WOF + b * 40960;
        const char* xb = sm + SM_XOF + b * 10240;
#pragma unroll
        for (int kk = 0; kk < 2; kk++) {
            int kb = kk * 32 + c4 * 4;
            uint32_t bh[4][2], bl[4][2];
#pragma unroll
            for (int nt = 0; nt < 4; nt++) {
                int prow = pxw + nt * 8 + g;
                bh[nt][0] = *(const uint32_t*)(xb + prow * W2P + kb);
                bh[nt][1] = *(const uint32_t*)(xb + prow * W2P + kb + 16);
                bl[nt][0] = *(const uint32_t*)(xb + 5120 + prow * W2P + kb);
                bl[nt][1] = *(const uint32_t*)(xb + 5120 + prow * W2P + kb + 16);
            }
#pragma unroll
            for (int mt = 0; mt < 4; mt++) {
                int orow = ow + mt * 16 + g;
                const char* wh = wb + orow * W2P + kb;
                const char* wl = wb + 20480 + orow * W2P + kb;
                uint32_t ah0 = *(const uint32_t*)(wh);
                uint32_t ah1 = *(const uint32_t*)(wh + 8 * W2P);
                uint32_t ah2 = *(const uint32_t*)(wh + 16);
                uint32_t ah3 = *(const uint32_t*)(wh + 8 * W2P + 16);
                uint32_t al0 = *(const uint32_t*)(wl);
                uint32_t al1 = *(const uint32_t*)(wl + 8 * W2P);
                uint32_t al2 = *(const uint32_t*)(wl + 16);
                uint32_t al3 = *(const uint32_t*)(wl + 8 * W2P + 16);
#pragma unroll
                for (int nt = 0; nt < 4; nt++) {
                    mma16816(d[mt][nt], ah0, ah1, ah2, ah3, bh[nt][0], bh[nt][1]);
                    mma16816(d[mt][nt], ah0, ah1, ah2, ah3, bl[nt][0], bl[nt][1]);
                    mma16816(d[mt][nt], al0, al1, al2, al3, bh[nt][0], bh[nt][1]);
                }
            }
        }
        __syncthreads();
    }
    // h = relu(D1*nrm[px] + bias1) -> smem [px][o] bf16 hi/lo
    {
        __nv_bfloat16* hh = (__nv_bfloat16*)(sm + SM_HOF);
        __nv_bfloat16* hl = (__nv_bfloat16*)(sm + SM_HOF + 64 * HPITCH);
#pragma unroll
        for (int mt = 0; mt < 4; mt++) {
#pragma unroll
            for (int nt = 0; nt < 4; nt++) {
                int oa = ow + mt * 16 + g, ob = oa + 8;
                int pa = pxw + nt * 8 + 2 * c4, pb = pa + 1;
                float na = nrms[pa], nb = nrms[pb];
                float v0 = fmaxf(d[mt][nt][0] * na + b1s[oa], 0.f);
                float v1 = fmaxf(d[mt][nt][1] * nb + b1s[oa], 0.f);
                float v2 = fmaxf(d[mt][nt][2] * na + b1s[ob], 0.f);
                float v3 = fmaxf(d[mt][nt][3] * nb + b1s[ob], 0.f);
                __nv_bfloat16 h0 = __float2bfloat16_rn(v0);
                __nv_bfloat16 h1 = __float2bfloat16_rn(v1);
                __nv_bfloat16 h2 = __float2bfloat16_rn(v2);
                __nv_bfloat16 h3 = __float2bfloat16_rn(v3);
                hh[pa * (HPITCH / 2) + oa] = h0;
                hh[pb * (HPITCH / 2) + oa] = h1;
                hh[pa * (HPITCH / 2) + ob] = h2;
                hh[pb * (HPITCH / 2) + ob] = h3;
                hl[pa * (HPITCH / 2) + oa] = __float2bfloat16_rn(v0 - __bfloat162float(h0));
                hl[pb * (HPITCH / 2) + oa] = __float2bfloat16_rn(v1 - __bfloat162float(h1));
                hl[pa * (HPITCH / 2) + ob] = __float2bfloat16_rn(v2 - __bfloat162float(h2));
                hl[pb * (HPITCH / 2) + ob] = __float2bfloat16_rn(v3 - __bfloat162float(h3));
                d[mt][nt][0] = 0.f; d[mt][nt][1] = 0.f;
                d[mt][nt][2] = 0.f; d[mt][nt][3] = 0.f;
            }
        }
    }
    __syncthreads();

    // ================= stage 2: D2 = W2 @ h =================
    ISSUE_W(g_w2hi, g_w2lo, 0, 0);
    CP_COMMIT();
#pragma unroll 1
    for (int kc = 0; kc < 8; kc++) {
        int b = kc & 1;
        if (kc < 7) {
            ISSUE_W(g_w2hi, g_w2lo, kc + 1, 1 - b);
            CP_COMMIT();
            CP_WAIT1();
        } else {
            CP_WAIT0();
        }
        __syncthreads();
        const char* wb = sm + SM_WOF + b * 40960;
#pragma unroll
        for (int kk = 0; kk < 2; kk++) {
            int kb = kk * 32 + c4 * 4;
            int kbh = kc * 64 + kk * 32 + c4 * 4;
            uint32_t bh[4][2], bl[4][2];
#pragma unroll
            for (int nt = 0; nt < 4; nt++) {
                int prow = pxw + nt * 8 + g;
                bh[nt][0] = *(const uint32_t*)(sm + SM_HOF + prow * HPITCH + kbh);
                bh[nt][1] = *(const uint32_t*)(sm + SM_HOF + prow * HPITCH + kbh + 16);
                bl[nt][0] = *(const uint32_t*)(sm + SM_HOF + 64 * HPITCH + prow * HPITCH + kbh);
                bl[nt][1] = *(const uint32_t*)(sm + SM_HOF + 64 * HPITCH + prow * HPITCH + kbh + 16);
            }
#pragma unroll
            for (int mt = 0; mt < 4; mt++) {
                int orow = ow + mt * 16 + g;
                const char* wh = wb + orow * W2P + kb;
                const char* wl = wb + 20480 + orow * W2P + kb;
                uint32_t ah0 = *(const uint32_t*)(wh);
                uint32_t ah1 = *(const uint32_t*)(wh + 8 * W2P);
                uint32_t ah2 = *(const uint32_t*)(wh + 16);
                uint32_t ah3 = *(const uint32_t*)(wh + 8 * W2P + 16);
                uint32_t al0 = *(const uint32_t*)(wl);
                uint32_t al1 = *(const uint32_t*)(wl + 8 * W2P);
                uint32_t al2 = *(const uint32_t*)(wl + 16);
                uint32_t al3 = *(const uint32_t*)(wl + 8 * W2P + 16);
#pragma unroll
                for (int nt = 0; nt < 4; nt++) {
                    mma16816(d[mt][nt], ah0, ah1, ah2, ah3, bh[nt][0], bh[nt][1]);
                    mma16816(d[mt][nt], ah0, ah1, ah2, ah3, bl[nt][0], bl[nt][1]);
                    mma16816(d[mt][nt], al0, al1, al2, al3, bh[nt][0], bh[nt][1]);
                }
            }
        }
        __syncthreads();
    }
    // epilogue
    {
        float* epi = (float*)(sm + SM_HOF);
#pragma unroll
        for (int mt = 0; mt < 4; mt++) {
#pragma unroll
            for (int nt = 0; nt < 4; nt++) {
                int oa = ow + mt * 16 + g, ob = oa + 8;
                int pa = pxw + nt * 8 + 2 * c4, pb = pa + 1;
                epi[oa * 68 + pa] = fmaxf(d[mt][nt][0] + b2s[oa], 0.f);
                epi[oa * 68 + pb] = fmaxf(d[mt][nt][1] + b2s[oa], 0.f);
                epi[ob * 68 + pa] = fmaxf(d[mt][nt][2] + b2s[ob], 0.f);
                epi[ob * 68 + pb] = fmaxf(d[mt][nt][3] + b2s[ob], 0.f);
            }
        }
        __syncthreads();
        for (int i = tid; i < 16384; i += 256) {
            int o = i >> 6, px = i & 63;
            out[(size_t)(n * CC + o) * LL + p0 + px] = epi[o * 68 + px];
        }
    }
#undef ISSUE_W
#undef ISSUE_X
}

// ---------------- launch ----------------
extern "C" void kernel_launch(void* const* d_in, const int* in_sizes, int n_in,
                              void* d_out, int out_size) {
    (void)in_sizes; (void)n_in; (void)out_size;
    const float* feature   = (const float*)d_in[0];
    const float* conv_up_w = (const float*)d_in[1];
    const float* conv_up_b = (const float*)d_in[2];
    const float* centroids = (const float*)d_in[3];
    const float* upfc_w    = (const float*)d_in[4];
    const float* upfc_b    = (const float*)d_in[5];
    const float* t1_w      = (const float*)d_in[6];
    const float* t1_b      = (const float*)d_in[7];
    const float* t2_w      = (const float*)d_in[8];
    const float* t2_b      = (const float*)d_in[9];
    float* out = (float*)d_out;

    const int SMP = 256 * 68 * 4;       // k_prep dynamic smem
    const int SMU = 41472 * 2;          // k_up0 dynamic smem (82944 B)
    cudaFuncSetAttribute(k_prep, cudaFuncAttributeMaxDynamicSharedMemorySize, SMP);
    cudaFuncSetAttribute(k_up0, cudaFuncAttributeMaxDynamicSharedMemorySize, SMU);
    cudaFuncSetAttribute(k_transform_mma, cudaFuncAttributeMaxDynamicSharedMemorySize, SM_TOT);

    k_wprep_all<<<544, 256>>>(conv_up_w, t1_w, t2_w);
    k_prep<<<dim3(64, 16), 256, SMP>>>(feature);
    k_conv_mma<<<dim3(4, 4, 16), 256>>>(conv_up_b);
    k_up0<<<dim3(16, 16), 256, SMU>>>(feature);
    k_upnorm<<<NN, 256>>>(centroids);
    k_fc<<<dim3(16, JS), 256>>>(upfc_w);
    k_bias1<<<NN, 256>>>(upfc_b, t1_w, t1_b);
    k_transform_mma<<<dim3(64, 16), 256, SM_TOT>>>(t2_b, out);
}

// round 17
// speedup vs baseline: 1.0174x; 1.0174x over previous
#include <cuda_runtime.h>
#include <cuda_bf16.h>
#include <cstdint>
#include <math.h>

#define NN 16
#define CC 256
#define HH 64
#define WW 64
#define LL 4096
#define KK 32
#define EPSV 1e-12f
#define SPL 16   // L-splits for k_up0
#define JS  32   // j-splits for FC

// ---------------- scratch (device globals; no allocation) ----------------
__device__ __nv_bfloat16 g_xci_hi[(size_t)NN * LL * CC];  // 32 MB: NORMALIZED feature bf16 hi, [n][l][c]
__device__ __nv_bfloat16 g_xci_lo[(size_t)NN * LL * CC];  // 32 MB: NORMALIZED feature bf16 lo
__device__ float g_inv[NN * LL];              // per-pixel 1/||f||
__device__ float g_nrm[NN * LL];              // per-pixel max(||f||, eps)
__device__ float g_sa[NN * KK * LL];          // 8 MB : sa' = softmax * inv[pixel]
__device__ float g_ssumc[NN * 16 * KK];       // ssum partials per conv CTA tile
__device__ float g_up0p[SPL * NN * KK * CC];  // 8 MB : einsum partials per L-split
__device__ float g_upn[NN * KK * CC];         // fully normalized up
__device__ float g_fcp[JS * NN * CC];         // FC partials
__device__ float g_bias1[NN * CC];            // effective t1 bias
__device__ __nv_bfloat16 g_cwhi[9 * 16 * 32 * 16];  // conv W split: [tap][chunk][m][k]
__device__ __nv_bfloat16 g_cwlo[9 * 16 * 32 * 16];
__device__ __nv_bfloat16 g_w1hi[CC * CC];     // t1_w (first 256 in-chans) split
__device__ __nv_bfloat16 g_w1lo[CC * CC];
__device__ __nv_bfloat16 g_w2hi[CC * CC];     // t2_w split
__device__ __nv_bfloat16 g_w2lo[CC * CC];

static __device__ __forceinline__ uint32_t pk2(__nv_bfloat16 a, __nv_bfloat16 b) {
    return (uint32_t)__bfloat16_as_ushort(a) | ((uint32_t)__bfloat16_as_ushort(b) << 16);
}
static __device__ __forceinline__ void mma16816(float* d,
                                                uint32_t a0, uint32_t a1, uint32_t a2, uint32_t a3,
                                                uint32_t b0, uint32_t b1) {
    asm volatile("mma.sync.aligned.m16n8k16.row.col.f32.bf16.bf16.f32 "
                 "{%0,%1,%2,%3}, {%4,%5,%6,%7}, {%8,%9}, {%0,%1,%2,%3};"
                 : "+f"(d[0]), "+f"(d[1]), "+f"(d[2]), "+f"(d[3])
                 : "r"(a0), "r"(a1), "r"(a2), "r"(a3), "r"(b0), "r"(b1));
}
__device__ __forceinline__ uint32_t smem_u32(const void* p) {
    uint32_t a;
    asm("{ .reg .u64 t; cvta.to.shared.u64 t, %1; cvt.u32.u64 %0, t; }" : "=r"(a) : "l"(p));
    return a;
}
#define CP16(dst, src) asm volatile("cp.async.cg.shared.global [%0], [%1], 16;" :: "r"(dst), "l"(src) : "memory")
#define CP_COMMIT()    asm volatile("cp.async.commit_group;" ::: "memory")
#define CP_WAIT1()     asm volatile("cp.async.wait_group 1;" ::: "memory")
#define CP_WAIT0()     asm volatile("cp.async.wait_group 0;" ::: "memory")

// ---------------- kernel 1: prep — normalize in smem, write NORMALIZED split ----------------
__global__ __launch_bounds__(256) void k_prep(const float* __restrict__ f) {
    extern __shared__ float sx[];   // [256 c][68 px-pitch]
    __shared__ float part[4][64];
    __shared__ float invv[64];
    int n = blockIdx.y;
    int l0 = blockIdx.x * 64;
    int tid = threadIdx.x;
    for (int i = tid; i < 4096; i += 256) {
        int c = i >> 4, p4 = (i & 15) << 2;
        float4 v = *(const float4*)(f + ((size_t)n * CC + c) * LL + l0 + p4);
        *(float4*)&sx[c * 68 + p4] = v;
    }
    __syncthreads();
    int px = tid & 63, q = tid >> 6;
    {
        float s = 0.f;
#pragma unroll 8
        for (int j = 0; j < 64; j++) {
            float v = sx[(q * 64 + j) * 68 + px];
            s += v * v;
        }
        part[q][px] = s;
    }
    __syncthreads();
    if (tid < 64) {
        float s = part[0][tid] + part[1][tid] + part[2][tid] + part[3][tid];
        float nr = fmaxf(sqrtf(s), EPSV);
        float iv = 1.f / nr;
        invv[tid] = iv;
        g_inv[n * LL + l0 + tid] = iv;
        g_nrm[n * LL + l0 + tid] = nr;
    }
    __syncthreads();
    float iv = invv[px];
    size_t cib = ((size_t)n * LL + l0 + px) * CC + q * 64;
#pragma unroll 2
    for (int j8 = 0; j8 < 64; j8 += 8) {
        uint32_t oh[4], ol[4];
#pragma unroll
        for (int t = 0; t < 4; t++) {
            float x0 = sx[(q * 64 + j8 + 2 * t) * 68 + px] * iv;
            float x1 = sx[(q * 64 + j8 + 2 * t + 1) * 68 + px] * iv;
            __nv_bfloat16 h0 = __float2bfloat16_rn(x0), h1 = __float2bfloat16_rn(x1);
            oh[t] = pk2(h0, h1);
            ol[t] = pk2(__float2bfloat16_rn(x0 - __bfloat162float(h0)),
                        __float2bfloat16_rn(x1 - __bfloat162float(h1)));
        }
        *(uint4*)(g_xci_hi + cib + j8) = make_uint4(oh[0], oh[1], oh[2], oh[3]);
        *(uint4*)(g_xci_lo + cib + j8) = make_uint4(ol[0], ol[1], ol[2], ol[3]);
    }
}

// ---------------- prep: conv weights + t1/t2 weights, one launch ----------------
__global__ __launch_bounds__(256) void k_wprep_all(const float* __restrict__ w,
                                                   const float* __restrict__ t1w,
                                                   const float* __restrict__ t2w) {
    int b = blockIdx.x;
    int tid = threadIdx.x;
    if (b < 288) {
        int i = b * 256 + tid;
        int t = i >> 13;
        int r = i & 8191;
        int chn = r >> 9;
        int m = (r >> 4) & 31;
        int kk = r & 15;
        int c = chn * 16 + kk;
        float x = w[((size_t)m * CC + c) * 9 + t];
        __nv_bfloat16 h = __float2bfloat16_rn(x);
        g_cwhi[i] = h;
        g_cwlo[i] = __float2bfloat16_rn(x - __bfloat162float(h));
    } else {
        int i = (b - 288) * 256 + tid;
        int o = i >> 8, c = i & 255;
        {
            float x = t1w[(size_t)o * 512 + c];
            __nv_bfloat16 h = __float2bfloat16_rn(x);
            g_w1hi[i] = h;
            g_w1lo[i] = __float2bfloat16_rn(x - __bfloat162float(h));
        }
        {
            float x = t2w[i];
            __nv_bfloat16 h = __float2bfloat16_rn(x);
            g_w2hi[i] = h;
            g_w2lo[i] = __float2bfloat16_rn(x - __bfloat162float(h));
        }
    }
}

// ---------------- kernel 2: 3x3 conv (16x16 tiles) + fused softmax ----------------
__global__ __launch_bounds__(256) void k_conv_mma(const float* __restrict__ bias) {
    __shared__ __align__(16) __nv_bfloat16 hHi[18 * 18 * 16];
    __shared__ __align__(16) __nv_bfloat16 hLo[18 * 18 * 16];
    __shared__ __align__(16) __nv_bfloat16 wHi[9 * 32 * 16];
    __shared__ __align__(16) __nv_bfloat16 wLo[9 * 32 * 16];
    __shared__ float sInv[256];
    __shared__ float sred[8][33];
    __shared__ float bsm[32];
    int n = blockIdx.z;
    int ty0 = blockIdx.y * 16, tx0 = blockIdx.x * 16;
    int tid = threadIdx.x, wid = tid >> 5, lane = tid & 31;
    int g = lane >> 2, c4 = lane & 3;
    if (tid < 32) bsm[tid] = bias[tid];
    sInv[tid] = g_inv[n * LL + (ty0 + (tid >> 4)) * 64 + tx0 + (tid & 15)];

    float d[2][4][4];
#pragma unroll
    for (int mt = 0; mt < 2; mt++)
#pragma unroll
        for (int nt = 0; nt < 4; nt++)
#pragma unroll
            for (int e = 0; e < 4; e++) d[mt][nt][e] = 0.f;

#pragma unroll 1
    for (int chk = 0; chk < 16; chk++) {
        int c0 = chk * 16;
        __syncthreads();
        for (int i = tid; i < 648; i += 256) {
            int slot = i >> 1, half = i & 1;
            int y = slot / 18, x = slot - y * 18;
            int gy = ty0 + y - 1, gx = tx0 + x - 1;
            uint4 vh = make_uint4(0, 0, 0, 0), vl = make_uint4(0, 0, 0, 0);
            if ((unsigned)gy < 64u && (unsigned)gx < 64u) {
                size_t off = ((size_t)n * LL + gy * 64 + gx) * CC + c0 + half * 8;
                vh = *(const uint4*)(g_xci_hi + off);
                vl = *(const uint4*)(g_xci_lo + off);
            }
            *(uint4*)(hHi + slot * 16 + half * 8) = vh;
            *(uint4*)(hLo + slot * 16 + half * 8) = vl;
        }
        for (int i = tid; i < 576; i += 256) {
            int t = i >> 6, r = i & 63;
            ((uint4*)wHi)[t * 64 + r] = ((const uint4*)g_cwhi)[(t * 16 + chk) * 64 + r];
            ((uint4*)wLo)[t * 64 + r] = ((const uint4*)g_cwlo)[(t * 16 + chk) * 64 + r];
        }
        __syncthreads();
#pragma unroll
        for (int tap = 0; tap < 9; tap++) {
            int r = tap / 3, s = tap - 3 * (tap / 3);
            uint32_t bh[4][2], bl[4][2];
#pragma unroll
            for (int nt = 0; nt < 4; nt++) {
                int pxl = wid * 32 + nt * 8 + g;
                int y = (pxl >> 4) + r, x = (pxl & 15) + s;
                const __nv_bfloat16* ph = hHi + (y * 18 + x) * 16 + 2 * c4;
                const __nv_bfloat16* pl = hLo + (y * 18 + x) * 16 + 2 * c4;
                bh[nt][0] = *(const uint32_t*)ph;
                bh[nt][1] = *(const uint32_t*)(ph + 8);
                bl[nt][0] = *(const uint32_t*)pl;
                bl[nt][1] = *(const uint32_t*)(pl + 8);
            }
#pragma unroll
            for (int mt = 0; mt < 2; mt++) {
                const __nv_bfloat16* qh = wHi + (tap * 32 + mt * 16 + g) * 16 + 2 * c4;
                const __nv_bfloat16* ql = wLo + (tap * 32 + mt * 16 + g) * 16 + 2 * c4;
                uint32_t ah0 = *(const uint32_t*)qh;
                uint32_t ah1 = *(const uint32_t*)(qh + 128);
                uint32_t ah2 = *(const uint32_t*)(qh + 8);
                uint32_t ah3 = *(const uint32_t*)(qh + 136);
                uint32_t al0 = *(const uint32_t*)ql;
                uint32_t al1 = *(const uint32_t*)(ql + 128);
                uint32_t al2 = *(const uint32_t*)(ql + 8);
                uint32_t al3 = *(const uint32_t*)(ql + 136);
#pragma unroll
                for (int nt = 0; nt < 4; nt++) {
                    mma16816(d[mt][nt], ah0, ah1, ah2, ah3, bh[nt][0], bh[nt][1]);
                    mma16816(d[mt][nt], ah0, ah1, ah2, ah3, bl[nt][0], bl[nt][1]);
                    mma16816(d[mt][nt], al0, al1, al2, al3, bh[nt][0], bh[nt][1]);
                }
            }
        }
    }
#pragma unroll
    for (int mt = 0; mt < 2; mt++)
#pragma unroll
        for (int nt = 0; nt < 4; nt++)
#pragma unroll
            for (int e = 0; e < 4; e++)
                d[mt][nt][e] += bsm[mt * 16 + g + (e >> 1) * 8];
    float ssacc[4] = {0.f, 0.f, 0.f, 0.f};
#pragma unroll
    for (int nt = 0; nt < 4; nt++) {
#pragma unroll
        for (int e1 = 0; e1 < 2; e1++) {
            float v00 = d[0][nt][e1], v01 = d[0][nt][e1 + 2];
            float v10 = d[1][nt][e1], v11 = d[1][nt][e1 + 2];
            float m = fmaxf(fmaxf(v00, v01), fmaxf(v10, v11));
            m = fmaxf(m, __shfl_xor_sync(0xffffffffu, m, 4));
            m = fmaxf(m, __shfl_xor_sync(0xffffffffu, m, 8));
            m = fmaxf(m, __shfl_xor_sync(0xffffffffu, m, 16));
            float e00 = __expf(v00 - m), e01 = __expf(v01 - m);
            float e10 = __expf(v10 - m), e11 = __expf(v11 - m);
            float s = e00 + e01 + e10 + e11;
            s += __shfl_xor_sync(0xffffffffu, s, 4);
            s += __shfl_xor_sync(0xffffffffu, s, 8);
            s += __shfl_xor_sync(0xffffffffu, s, 16);
            float inv = 1.f / s;
            float sa00 = e00 * inv, sa01 = e01 * inv;
            float sa10 = e10 * inv, sa11 = e11 * inv;
            ssacc[0] += sa00; ssacc[1] += sa01;
            ssacc[2] += sa10; ssacc[3] += sa11;
            int px = wid * 32 + nt * 8 + 2 * c4 + e1;
            float pxinv = sInv[px];
            int gy = ty0 + (px >> 4), gx = tx0 + (px & 15);
            size_t base = ((size_t)n * KK) * LL + gy * 64 + gx;
            g_sa[base + (size_t)g * LL]        = sa00 * pxinv;
            g_sa[base + (size_t)(g + 8) * LL]  = sa01 * pxinv;
            g_sa[base + (size_t)(g + 16) * LL] = sa10 * pxinv;
            g_sa[base + (size_t)(g + 24) * LL] = sa11 * pxinv;
        }
    }
#pragma unroll
    for (int j = 0; j < 4; j++) {
        ssacc[j] += __shfl_xor_sync(0xffffffffu, ssacc[j], 1);
        ssacc[j] += __shfl_xor_sync(0xffffffffu, ssacc[j], 2);
    }
    if (c4 == 0) {
        sred[wid][g]      = ssacc[0];
        sred[wid][g + 8]  = ssacc[1];
        sred[wid][g + 16] = ssacc[2];
        sred[wid][g + 24] = ssacc[3];
    }
    __syncthreads();
    if (tid < 32) {
        float t = 0.f;
#pragma unroll
        for (int w = 0; w < 8; w++) t += sred[w][tid];
        int tile = blockIdx.y * 4 + blockIdx.x;
        g_ssumc[(n * 16 + tile) * KK + tid] = t;
    }
}

// ---------------- kernel 4: einsum partials via mma.sync (R13/R15 proven config) ----------------
#define UPITCH 72
__global__ __launch_bounds__(256, 3) void k_up0(const float* __restrict__ f) {
    __shared__ __align__(16) __nv_bfloat16 saH[KK * UPITCH];
    __shared__ __align__(16) __nv_bfloat16 saL[KK * UPITCH];
    __shared__ __align__(16) __nv_bfloat16 fHs[128 * UPITCH];
    __shared__ __align__(16) __nv_bfloat16 fLs[128 * UPITCH];
    int n = blockIdx.y;
    int sp = blockIdx.z;
    int cbase = blockIdx.x * 128;
    int lbase = sp * (LL / SPL);
    int tid = threadIdx.x, wid = tid >> 5, lane = tid & 31;
    int g = lane >> 2, c4 = lane & 3;
    int c0w = wid * 16;

    float d[2][2][4];
#pragma unroll
    for (int mt = 0; mt < 2; mt++)
#pragma unroll
        for (int nt = 0; nt < 2; nt++)
#pragma unroll
            for (int e = 0; e < 4; e++) d[mt][nt][e] = 0.f;

#pragma unroll 1
    for (int ch = 0; ch < 4; ch++) {
        int l0 = lbase + ch * 64;
        __syncthreads();
        for (int i = tid; i < 512; i += 256) {
            int k = i >> 4, l4 = (i & 15) << 2;
            float4 v = *(const float4*)(g_sa + (size_t)(n * KK + k) * LL + l0 + l4);
            __nv_bfloat16 h0 = __float2bfloat16_rn(v.x), h1 = __float2bfloat16_rn(v.y);
            __nv_bfloat16 h2 = __float2bfloat16_rn(v.z), h3 = __float2bfloat16_rn(v.w);
            *(uint2*)&saH[k * UPITCH + l4] = make_uint2(pk2(h0, h1), pk2(h2, h3));
            *(uint2*)&saL[k * UPITCH + l4] = make_uint2(
                pk2(__float2bfloat16_rn(v.x - __bfloat162float(h0)),
                    __float2bfloat16_rn(v.y - __bfloat162float(h1))),
                pk2(__float2bfloat16_rn(v.z - __bfloat162float(h2)),
                    __float2bfloat16_rn(v.w - __bfloat162float(h3))));
        }
        for (int i = tid; i < 2048; i += 256) {
            int c = i >> 4, l4 = (i & 15) << 2;
            float4 v = *(const float4*)(f + (size_t)(n * CC + cbase + c) * LL + l0 + l4);
            __nv_bfloat16 h0 = __float2bfloat16_rn(v.x), h1 = __float2bfloat16_rn(v.y);
            __nv_bfloat16 h2 = __float2bfloat16_rn(v.z), h3 = __float2bfloat16_rn(v.w);
            *(uint2*)&fHs[c * UPITCH + l4] = make_uint2(pk2(h0, h1), pk2(h2, h3));
            *(uint2*)&fLs[c * UPITCH + l4] = make_uint2(
                pk2(__float2bfloat16_rn(v.x - __bfloat162float(h0)),
                    __float2bfloat16_rn(v.y - __bfloat162float(h1))),
                pk2(__float2bfloat16_rn(v.z - __bfloat162float(h2)),
                    __float2bfloat16_rn(v.w - __bfloat162float(h3))));
        }
        __syncthreads();
#pragma unroll
        for (int ls = 0; ls < 4; ls++) {
            int cb = ls * 16 + 2 * c4;
            uint32_t aH[2][4], aL[2][4];
#pragma unroll
            for (int mt = 0; mt < 2; mt++) {
                int r0 = mt * 16 + g;
                aH[mt][0] = *(const uint32_t*)&saH[r0 * UPITCH + cb];
                aH[mt][1] = *(const uint32_t*)&saH[(r0 + 8) * UPITCH + cb];
                aH[mt][2] = *(const uint32_t*)&saH[r0 * UPITCH + cb + 8];
                aH[mt][3] = *(const uint32_t*)&saH[(r0 + 8) * UPITCH + cb + 8];
                aL[mt][0] = *(const uint32_t*)&saL[r0 * UPITCH + cb];
                aL[mt][1] = *(const uint32_t*)&saL[(r0 + 8) * UPITCH + cb];
                aL[mt][2] = *(const uint32_t*)&saL[r0 * UPITCH + cb + 8];
                aL[mt][3] = *(const uint32_t*)&saL[(r0 + 8) * UPITCH + cb + 8];
            }
            uint32_t bH[2][2], bL[2][2];
#pragma unroll
            for (int nt = 0; nt < 2; nt++) {
                int crow = c0w + nt * 8 + g;
                bH[nt][0] = *(const uint32_t*)&fHs[crow * UPITCH + cb];
                bH[nt][1] = *(const uint32_t*)&fHs[crow * UPITCH + cb + 8];
                bL[nt][0] = *(const uint32_t*)&fLs[crow * UPITCH + cb];
                bL[nt][1] = *(const uint32_t*)&fLs[crow * UPITCH + cb + 8];
            }
#pragma unroll
            for (int mt = 0; mt < 2; mt++)
#pragma unroll
                for (int nt = 0; nt < 2; nt++) {
                    mma16816(d[mt][nt], aH[mt][0], aH[mt][1], aH[mt][2], aH[mt][3],
                             bH[nt][0], bH[nt][1]);
                    mma16816(d[mt][nt], aH[mt][0], aH[mt][1], aH[mt][2], aH[mt][3],
                             bL[nt][0], bL[nt][1]);
                    mma16816(d[mt][nt], aL[mt][0], aL[mt][1], aL[mt][2], aL[mt][3],
                             bH[nt][0], bH[nt][1]);
                }
        }
    }
    size_t ob = ((size_t)sp * NN + n) * (KK * CC);
#pragma unroll
    for (int mt = 0; mt < 2; mt++) {
#pragma unroll
        for (int nt = 0; nt < 2; nt++) {
            int k0 = mt * 16 + g;
            int cc = cbase + c0w + nt * 8 + 2 * c4;
            *(float2*)(g_up0p + ob + (size_t)k0 * CC + cc) = make_float2(d[mt][nt][0], d[mt][nt][1]);
            *(float2*)(g_up0p + ob + (size_t)(k0 + 8) * CC + cc) = make_float2(d[mt][nt][2], d[mt][nt][3]);
        }
    }
}

// ---------------- kernel 5a: reduce partials + centroid-sub + norms -> g_upn ----------------
__global__ __launch_bounds__(256) void k_upnorm(const float* __restrict__ cent) {
    int n = blockIdx.x;
    int tid = threadIdx.x;
    int lane = tid & 31, wp = tid >> 5;
    __shared__ float upn[KK * CC];
    __shared__ float red[8];
    __shared__ float ssk[KK];
    __shared__ float gtot;

    if (tid < KK) {
        float s = 0.f;
#pragma unroll
        for (int t = 0; t < 16; t++)
            s += g_ssumc[(n * 16 + t) * KK + tid];
        ssk[tid] = s;
    }
    __syncthreads();

    for (int k = wp; k < KK; k += 8) {
        float sk = ssk[k];
        float vals[8];
        float sq = 0.f;
#pragma unroll
        for (int j = 0; j < 8; j++) {
            int c = lane + 32 * j;
            float u = 0.f;
#pragma unroll
            for (int sp = 0; sp < SPL; sp++)
                u += g_up0p[((size_t)sp * NN + n) * (KK * CC) + k * CC + c];
            u -= sk * cent[k * CC + c];
            vals[j] = u;
            sq += u * u;
        }
        for (int off = 16; off; off >>= 1) sq += __shfl_xor_sync(0xffffffffu, sq, off);
        float inv = 1.f / fmaxf(sqrtf(sq), EPSV);
#pragma unroll
        for (int j = 0; j < 8; j++) upn[k * CC + lane + 32 * j] = vals[j] * inv;
    }
    __syncthreads();
    float gs = 0.f;
#pragma unroll 4
    for (int j = 0; j < 32; j++) {
        float v = upn[j * 256 + tid];
        gs += v * v;
    }
    for (int off = 16; off; off >>= 1) gs += __shfl_xor_sync(0xffffffffu, gs, off);
    if (!lane) red[wp] = gs;
    __syncthreads();
    if (tid == 0) {
        float t = 0.f;
        for (int i = 0; i < 8; i++) t += red[i];
        gtot = 1.f / fmaxf(sqrtf(t), EPSV);
    }
    __syncthreads();
    float ginv = gtot;
#pragma unroll 4
    for (int j = 0; j < 32; j++)
        g_upn[n * (KK * CC) + j * 256 + tid] = upn[j * 256 + tid] * ginv;
}

// ---------------- kernel 5b: FC partials ----------------
#define FCP 264
__global__ __launch_bounds__(256) void k_fc(const float* __restrict__ wfc) {
    __shared__ float ws[16][FCP];
    __shared__ float us2[16][FCP];
    int ot = blockIdx.x * 16;
    int j0 = blockIdx.y * 256;
    int tid = threadIdx.x;
    for (int i = tid; i < 16 * 64; i += 256) {
        int row = i >> 6, j4 = (i & 63) << 2;
        *(float4*)&ws[row][j4] = *(const float4*)(wfc + (size_t)(ot + row) * (KK * CC) + j0 + j4);
        *(float4*)&us2[row][j4] = *(const float4*)(g_upn + (size_t)row * (KK * CC) + j0 + j4);
    }
    __syncthreads();
    int o = tid & 15, n = tid >> 4;
    float s = 0.f;
#pragma unroll 8
    for (int jj = 0; jj < 64; jj++) {
        float4 a = *(const float4*)&ws[o][jj * 4];
        float4 b = *(const float4*)&us2[n][jj * 4];
        s += a.x * b.x + a.y * b.y + a.z * b.z + a.w * b.w;
    }
    g_fcp[(size_t)(blockIdx.y * NN + n) * CC + ot + o] = s;
}

// ---------------- kernel 5c: FC reduce + effective t1 bias (merged) ----------------
__global__ __launch_bounds__(256) void k_bias1(const float* __restrict__ bfc,
                                               const float* __restrict__ t1w,
                                               const float* __restrict__ t1b) {
    __shared__ float ufc[CC];
    int n = blockIdx.x;
    int tid = threadIdx.x;
    float s = 0.f;
#pragma unroll
    for (int js = 0; js < JS; js++)
        s += g_fcp[(size_t)(js * NN + n) * CC + tid];
    ufc[tid] = s + bfc[tid];
    __syncthreads();
    float b = 0.f;
#pragma unroll 8
    for (int c = 0; c < CC; c += 4) {
        float4 wv = *(const float4*)(t1w + (size_t)tid * 512 + 256 + c);
        b += wv.x * ufc[c] + wv.y * ufc[c + 1] + wv.z * ufc[c + 2] + wv.w * ufc[c + 3];
    }
    g_bias1[n * CC + tid] = t1b[tid] + b;
}

// ---------------- kernel 6: mma.sync transform, cp.async double-buffered ----------------
#define W2P    80
#define SM_WOF 2048
#define SM_XOF 83968
#define SM_HOF 104448
#define SM_TOT 174080
#define HPITCH 528

__global__ __launch_bounds__(256, 1) void k_transform_mma(const float* __restrict__ t2b,
                                                          float* __restrict__ out) {
    extern __shared__ char sm[];
    __shared__ float nrms[64];
    uint32_t sb = smem_u32(sm);
    float* b1s = (float*)sm;
    float* b2s = (float*)(sm + 1024);
    int tid = threadIdx.x;
    int wid = tid >> 5, lane = tid & 31;
    int g = lane >> 2, c4 = lane & 3;
    int ow = (wid >> 1) * 64;
    int pxw = (wid & 1) * 32;
    int n = blockIdx.y;
    int p0 = blockIdx.x * 64;

    b1s[tid] = g_bias1[n * CC + tid];
    b2s[tid] = t2b[tid];
    if (tid < 64) nrms[tid] = g_nrm[n * LL + p0 + tid];

#define ISSUE_W(whi, wlo, kc, b)                                                   \
    do {                                                                           \
        uint32_t wb_ = sb + SM_WOF + (b) * 40960;                                  \
        for (int i_ = tid; i_ < 2048; i_ += 256) {                                 \
            int half_ = i_ >> 10;                                                  \
            int r_ = i_ & 1023;                                                    \
            int o_ = r_ >> 2, j_ = r_ & 3;                                         \
            const __nv_bfloat16* s_ = (half_ ? (wlo) : (whi)) + o_ * 256 + (kc) * 32 + j_ * 8; \
            CP16(wb_ + half_ * 20480 + o_ * W2P + j_ * 16, s_);                    \
        }                                                                          \
    } while (0)
#define ISSUE_X(kc, b)                                                             \
    do {                                                                           \
        uint32_t xb_ = sb + SM_XOF + (b) * 10240;                                  \
        for (int i_ = tid; i_ < 512; i_ += 256) {                                  \
            int half_ = i_ >> 8;                                                   \
            int r_ = i_ & 255;                                                     \
            int px_ = r_ >> 2, j_ = r_ & 3;                                        \
            const __nv_bfloat16* s_ = (half_ ? g_xci_lo : g_xci_hi)                \
                + ((size_t)n * LL + p0 + px_) * CC + (kc) * 32 + j_ * 8;           \
            CP16(xb_ + half_ * 5120 + px_ * W2P + j_ * 16, s_);                    \
        }                                                                          \
    } while (0)

    float d[4][4][4];
#pragma unroll
    for (int mt = 0; mt < 4; mt++)
#pragma unroll
        for (int nt = 0; nt < 4; nt++)
#pragma unroll
            for (int e = 0; e < 4; e++) d[mt][nt][e] = 0.f;

    // ================= stage 1: D1 = W1 @ X (X normalized; rescale at epilogue) =================
    ISSUE_W(g_w1hi, g_w1lo, 0, 0);
    ISSUE_X(0, 0);
    CP_COMMIT();
#pragma unroll 1
    for (int kc = 0; kc < 8; kc++) {
        int b = kc & 1;
        if (kc < 7) {
            ISSUE_W(g_w1hi, g_w1lo, kc + 1, 1 - b);
            ISSUE_X(kc + 1, 1 - b);
            CP_COMMIT();
            CP_WAIT1();
        } else {
            CP_WAIT0();
        }
        __syncthreads();
        const char* wb = sm + SM_WOF + b * 40960;
        const char* xb = sm + SM_XOF + b * 10240;
#pragma unroll
        for (int kk = 0; kk < 2; kk++) {
            int kb = kk * 32 + c4 * 4;
            uint32_t bh[4][2], bl[4][2];
#pragma unroll
            for (int nt = 0; nt < 4; nt++) {
                int prow = pxw + nt * 8 + g;
                bh[nt][0] = *(const uint32_t*)(xb + prow * W2P + kb);
                bh[nt][1] = *(const uint32_t*)(xb + prow * W2P + kb + 16);
                bl[nt][0] = *(const uint32_t*)(xb + 5120 + prow * W2P + kb);
                bl[nt][1] = *(const uint32_t*)(xb + 5120 + prow * W2P + kb + 16);
            }
#pragma unroll
            for (int mt = 0; mt < 4; mt++) {
                int orow = ow + mt * 16 + g;
                const char* wh = wb + orow * W2P + kb;
                const char* wl = wb + 20480 + orow * W2P + kb;
                uint32_t ah0 = *(const uint32_t*)(wh);
                uint32_t ah1 = *(const uint32_t*)(wh + 8 * W2P);
                uint32_t ah2 = *(const uint32_t*)(wh + 16);
                uint32_t ah3 = *(const uint32_t*)(wh + 8 * W2P + 16);
                uint32_t al0 = *(const uint32_t*)(wl);
                uint32_t al1 = *(const uint32_t*)(wl + 8 * W2P);
                uint32_t al2 = *(const uint32_t*)(wl + 16);
                uint32_t al3 = *(const uint32_t*)(wl + 8 * W2P + 16);
#pragma unroll
                for (int nt = 0; nt < 4; nt++) {
                    mma16816(d[mt][nt], ah0, ah1, ah2, ah3, bh[nt][0], bh[nt][1]);
                    mma16816(d[mt][nt], ah0, ah1, ah2, ah3, bl[nt][0], bl[nt][1]);
                    mma16816(d[mt][nt], al0, al1, al2, al3, bh[nt][0], bh[nt][1]);
                }
            }
        }
        __syncthreads();
    }
    // h = relu(D1*nrm[px] + bias1) -> smem [px][o] bf16 hi/lo
    {
        __nv_bfloat16* hh = (__nv_bfloat16*)(sm + SM_HOF);
        __nv_bfloat16* hl = (__nv_bfloat16*)(sm + SM_HOF + 64 * HPITCH);
#pragma unroll
        for (int mt = 0; mt < 4; mt++) {
#pragma unroll
            for (int nt = 0; nt < 4; nt++) {
                int oa = ow + mt * 16 + g, ob = oa + 8;
                int pa = pxw + nt * 8 + 2 * c4, pb = pa + 1;
                float na = nrms[pa], nb = nrms[pb];
                float v0 = fmaxf(d[mt][nt][0] * na + b1s[oa], 0.f);
                float v1 = fmaxf(d[mt][nt][1] * nb + b1s[oa], 0.f);
                float v2 = fmaxf(d[mt][nt][2] * na + b1s[ob], 0.f);
                float v3 = fmaxf(d[mt][nt][3] * nb + b1s[ob], 0.f);
                __nv_bfloat16 h0 = __float2bfloat16_rn(v0);
                __nv_bfloat16 h1 = __float2bfloat16_rn(v1);
                __nv_bfloat16 h2 = __float2bfloat16_rn(v2);
                __nv_bfloat16 h3 = __float2bfloat16_rn(v3);
                hh[pa * (HPITCH / 2) + oa] = h0;
                hh[pb * (HPITCH / 2) + oa] = h1;
                hh[pa * (HPITCH / 2) + ob] = h2;
                hh[pb * (HPITCH / 2) + ob] = h3;
                hl[pa * (HPITCH / 2) + oa] = __float2bfloat16_rn(v0 - __bfloat162float(h0));
                hl[pb * (HPITCH / 2) + oa] = __float2bfloat16_rn(v1 - __bfloat162float(h1));
                hl[pa * (HPITCH / 2) + ob] = __float2bfloat16_rn(v2 - __bfloat162float(h2));
                hl[pb * (HPITCH / 2) + ob] = __float2bfloat16_rn(v3 - __bfloat162float(h3));
                d[mt][nt][0] = 0.f; d[mt][nt][1] = 0.f;
                d[mt][nt][2] = 0.f; d[mt][nt][3] = 0.f;
            }
        }
    }
    __syncthreads();

    // ================= stage 2: D2 = W2 @ h =================
    ISSUE_W(g_w2hi, g_w2lo, 0, 0);
    CP_COMMIT();
#pragma unroll 1
    for (int kc = 0; kc < 8; kc++) {
        int b = kc & 1;
        if (kc < 7) {
            ISSUE_W(g_w2hi, g_w2lo, kc + 1, 1 - b);
            CP_COMMIT();
            CP_WAIT1();
        } else {
            CP_WAIT0();
        }
        __syncthreads();
        const char* wb = sm + SM_WOF + b * 40960;
#pragma unroll
        for (int kk = 0; kk < 2; kk++) {
            int kb = kk * 32 + c4 * 4;
            int kbh = kc * 64 + kk * 32 + c4 * 4;
            uint32_t bh[4][2], bl[4][2];
#pragma unroll
            for (int nt = 0; nt < 4; nt++) {
                int prow = pxw + nt * 8 + g;
                bh[nt][0] = *(const uint32_t*)(sm + SM_HOF + prow * HPITCH + kbh);
                bh[nt][1] = *(const uint32_t*)(sm + SM_HOF + prow * HPITCH + kbh + 16);
                bl[nt][0] = *(const uint32_t*)(sm + SM_HOF + 64 * HPITCH + prow * HPITCH + kbh);
                bl[nt][1] = *(const uint32_t*)(sm + SM_HOF + 64 * HPITCH + prow * HPITCH + kbh + 16);
            }
#pragma unroll
            for (int mt = 0; mt < 4; mt++) {
                int orow = ow + mt * 16 + g;
                const char* wh = wb + orow * W2P + kb;
                const char* wl = wb + 20480 + orow * W2P + kb;
                uint32_t ah0 = *(const uint32_t*)(wh);
                uint32_t ah1 = *(const uint32_t*)(wh + 8 * W2P);
                uint32_t ah2 = *(const uint32_t*)(wh + 16);
                uint32_t ah3 = *(const uint32_t*)(wh + 8 * W2P + 16);
                uint32_t al0 = *(const uint32_t*)(wl);
                uint32_t al1 = *(const uint32_t*)(wl + 8 * W2P);
                uint32_t al2 = *(const uint32_t*)(wl + 16);
                uint32_t al3 = *(const uint32_t*)(wl + 8 * W2P + 16);
#pragma unroll
                for (int nt = 0; nt < 4; nt++) {
                    mma16816(d[mt][nt], ah0, ah1, ah2, ah3, bh[nt][0], bh[nt][1]);
                    mma16816(d[mt][nt], ah0, ah1, ah2, ah3, bl[nt][0], bl[nt][1]);
                    mma16816(d[mt][nt], al0, al1, al2, al3, bh[nt][0], bh[nt][1]);
                }
            }
        }
        __syncthreads();
    }
    // epilogue: relu(D2 + t2b) -> direct float2 stores (8-px runs per lane quad = full sectors)
    {
#pragma unroll
        for (int mt = 0; mt < 4; mt++) {
#pragma unroll
            for (int nt = 0; nt < 4; nt++) {
                int oa = ow + mt * 16 + g, ob = oa + 8;
                int pa = pxw + nt * 8 + 2 * c4;
                float2 va, vb;
                va.x = fmaxf(d[mt][nt][0] + b2s[oa], 0.f);
                va.y = fmaxf(d[mt][nt][1] + b2s[oa], 0.f);
                vb.x = fmaxf(d[mt][nt][2] + b2s[ob], 0.f);
                vb.y = fmaxf(d[mt][nt][3] + b2s[ob], 0.f);
                *(float2*)(out + (size_t)(n * CC + oa) * LL + p0 + pa) = va;
                *(float2*)(out + (size_t)(n * CC + ob) * LL + p0 + pa) = vb;
            }
        }
    }
#undef ISSUE_W
#undef ISSUE_X
}

// ---------------- launch ----------------
extern "C" void kernel_launch(void* const* d_in, const int* in_sizes, int n_in,
                              void* d_out, int out_size) {
    (void)in_sizes; (void)n_in; (void)out_size;
    const float* feature   = (const float*)d_in[0];
    const float* conv_up_w = (const float*)d_in[1];
    const float* conv_up_b = (const float*)d_in[2];
    const float* centroids = (const float*)d_in[3];
    const float* upfc_w    = (const float*)d_in[4];
    const float* upfc_b    = (const float*)d_in[5];
    const float* t1_w      = (const float*)d_in[6];
    const float* t1_b      = (const float*)d_in[7];
    const float* t2_w      = (const float*)d_in[8];
    const float* t2_b      = (const float*)d_in[9];
    float* out = (float*)d_out;

    const int SMP = 256 * 68 * 4;
    cudaFuncSetAttribute(k_prep, cudaFuncAttributeMaxDynamicSharedMemorySize, SMP);
    cudaFuncSetAttribute(k_transform_mma, cudaFuncAttributeMaxDynamicSharedMemorySize, SM_TOT);

    k_wprep_all<<<544, 256>>>(conv_up_w, t1_w, t2_w);
    k_prep<<<dim3(64, 16), 256, SMP>>>(feature);
    k_conv_mma<<<dim3(4, 4, 16), 256>>>(conv_up_b);
    k_up0<<<dim3(2, 16, SPL), 256>>>(feature);
    k_upnorm<<<NN, 256>>>(centroids);
    k_fc<<<dim3(16, JS), 256>>>(upfc_w);
    k_bias1<<<NN, 256>>>(upfc_b, t1_w, t1_b);
    k_transform_mma<<<dim3(64, 16), 256, SM_TOT>>>(t2_b, out);
}